// round 12
// baseline (speedup 1.0000x reference)
#include <cuda_runtime.h>
#include <math.h>

#define BATCH 8
#define NPTS 2048
#define KPT 128
#define THREADS 256
#define SLEN 64
#define NBLOCKS 568

// Encoded min-d^2 accumulators. u = ~__float_as_uint(max(d2,0)).
// Monotone-decreasing encoding: unsigned atomicMax == float min.
// All encoded values >= 0x80000000, so zero (initial / post-finalize reset)
// is the identity.
__device__ unsigned int g_min[2 * 16384];   // [dir*16384 + b*2048 + row]
__device__ unsigned int g_d3min[1024];      // [b*128 + r]
// slots: [0..15] dir2 item sums, [16..23] per-batch small losses
__device__ float g_slots[24];
__device__ unsigned int g_count;

__device__ __forceinline__ unsigned int enc_min(float d2) {
    return ~__float_as_uint(fmaxf(d2, 0.0f));
}
__device__ __forceinline__ float dec_sqrt(unsigned int u) {
    float x = __uint_as_float(~u);
    float r;
    asm("sqrt.approx.f32 %0, %1;" : "=f"(r) : "f"(x));
    return r;
}
__device__ __forceinline__ float sqrt_fast(float x) {
    float r;
    asm("sqrt.approx.f32 %0, %1;" : "=f"(r) : "f"(x));
    return r;
}

// block sum over 256 threads; result valid on tid 0.
__device__ __forceinline__ float block_sum(float v, float* red8) {
    const int tid = threadIdx.x;
    #pragma unroll
    for (int o = 16; o > 0; o >>= 1) v += __shfl_down_sync(0xFFFFFFFFu, v, o);
    if ((tid & 31) == 0) red8[tid >> 5] = v;
    __syncthreads();
    if (tid < 8) {
        v = red8[tid];
        #pragma unroll
        for (int o = 4; o > 0; o >>= 1) v += __shfl_down_sync(0xFFu, v, o);
    }
    return v;
}

__global__ void __launch_bounds__(THREADS, 4)
fused(const float* __restrict__ pts,
      const float* __restrict__ recon,
      const float* __restrict__ kpt,
      const float* __restrict__ recon_delta,
      const float* __restrict__ pred_nocs,
      const float* __restrict__ pred_R,
      const float* __restrict__ pred_t,
      const float* __restrict__ pred_s,
      const float* __restrict__ gt_R,
      const float* __restrict__ gt_t,
      const float* __restrict__ gt_s,
      float* __restrict__ out) {
    __shared__ __align__(16) unsigned char s_buf[8192];
    __shared__ float s_red[8];
    __shared__ unsigned int s_rank;

    const int bid = blockIdx.x;
    const int tid = threadIdx.x;

    if (bid < 512) {
        // ===== heavy: dir0/dir1, 2048 rows (8/thread), 64-target slice =====
        const int dir = bid >> 8;
        const int b   = (bid >> 5) & 7;
        const int s   = bid & 31;

        const float* Q = (dir == 0 ? pts : recon) + (size_t)b * NPTS * 3;
        const float* T = (dir == 0 ? recon : pts) + (size_t)b * NPTS * 3 + s * SLEN * 3;

        float4* tile = (float4*)s_buf;  // (-2x, -2y, -2z, |s|^2)
        if (tid < SLEN) {
            float x = T[tid * 3 + 0];
            float y = T[tid * 3 + 1];
            float z = T[tid * 3 + 2];
            float w = fmaf(x, x, fmaf(y, y, z * z));
            tile[tid] = make_float4(-2.0f * x, -2.0f * y, -2.0f * z, w);
        }
        __syncthreads();

        float qx[8], qy[8], qz[8], q2[8];
        #pragma unroll
        for (int q = 0; q < 8; q++) {
            const int r = tid + 256 * q;
            qx[q] = Q[r * 3 + 0];
            qy[q] = Q[r * 3 + 1];
            qz[q] = Q[r * 3 + 2];
            q2[q] = fmaf(qx[q], qx[q], fmaf(qy[q], qy[q], qz[q] * qz[q]));
        }

        float m[8];
        #pragma unroll
        for (int q = 0; q < 8; q++) m[q] = 3.0e38f;

        #pragma unroll 4
        for (int t = 0; t < SLEN; t++) {
            const float4 sv = tile[t];
            #pragma unroll
            for (int q = 0; q < 8; q++) {
                float v = fmaf(sv.x, qx[q], fmaf(sv.y, qy[q], fmaf(sv.z, qz[q], sv.w)));
                m[q] = fminf(m[q], v);
            }
        }

        unsigned int* dst = g_min + dir * 16384 + b * 2048;
        #pragma unroll
        for (int q = 0; q < 8; q++)
            atomicMax(&dst[tid + 256 * q], enc_min(q2[q] + m[q]));
    } else {
        const int id = bid - 512;
        if (id < 16) {
            // dir2: pts -> kpt, 1024-row half, full 128 targets (direct sum)
            const int b = id >> 1;
            const int half = id & 1;
            const float* Q = pts + (size_t)b * NPTS * 3;
            const float* T = kpt + (size_t)b * KPT * 3;
            float4* tile = (float4*)s_buf;
            if (tid < KPT) {
                float x = T[tid * 3 + 0];
                float y = T[tid * 3 + 1];
                float z = T[tid * 3 + 2];
                float w = fmaf(x, x, fmaf(y, y, z * z));
                tile[tid] = make_float4(-2.0f * x, -2.0f * y, -2.0f * z, w);
            }
            __syncthreads();

            const int rowbase = half * 1024;
            float sum = 0.0f;
            #pragma unroll
            for (int q = 0; q < 4; q++) {
                const int r = rowbase + tid + 256 * q;
                float qx = Q[r * 3 + 0];
                float qy = Q[r * 3 + 1];
                float qz = Q[r * 3 + 2];
                float q2 = fmaf(qx, qx, fmaf(qy, qy, qz * qz));
                float mm = 3.0e38f;
                #pragma unroll 8
                for (int t = 0; t < KPT; t++) {
                    float4 sv = tile[t];
                    float v = fmaf(sv.x, qx, fmaf(sv.y, qy, fmaf(sv.z, qz, sv.w)));
                    mm = fminf(mm, v);
                }
                sum += sqrt_fast(fmaxf(q2 + mm, 0.0f));
            }
            float tot = block_sum(sum, s_red);
            if (tid == 0) g_slots[id] = tot * (0.5f / (BATCH * NPTS));
        } else if (id < 48) {
            // dir3: kpt -> pts, 512-target quarter -> atomic min partial
            const int j = id - 16;
            const int b = j >> 2;
            const int quarter = j & 3;
            const float* Q = kpt + (size_t)b * KPT * 3;
            const float* T = pts + (size_t)b * NPTS * 3 + quarter * 512 * 3;
            float4* tile = (float4*)s_buf;
            for (int jj = tid; jj < 512; jj += THREADS) {
                float x = T[jj * 3 + 0];
                float y = T[jj * 3 + 1];
                float z = T[jj * 3 + 2];
                float w = fmaf(x, x, fmaf(y, y, z * z));
                tile[jj] = make_float4(-2.0f * x, -2.0f * y, -2.0f * z, w);
            }
            __syncthreads();

            if (tid < KPT) {
                float qx = Q[tid * 3 + 0];
                float qy = Q[tid * 3 + 1];
                float qz = Q[tid * 3 + 2];
                float q2 = fmaf(qx, qx, fmaf(qy, qy, qz * qz));
                float mm = 3.0e38f;
                #pragma unroll 8
                for (int t = 0; t < 512; t++) {
                    float4 sv = tile[t];
                    float v = fmaf(sv.x, qx, fmaf(sv.y, qy, fmaf(sv.z, qz, sv.w)));
                    mm = fminf(mm, v);
                }
                atomicMax(&g_d3min[b * KPT + tid], enc_min(q2 + mm));
            }
        } else {
            // smalls: pose + NOCS + diversity + delta per batch
            const int b = id - 48;
            float* sk = (float*)s_buf;
            const float* K = kpt + (size_t)b * KPT * 3;
            for (int i = tid; i < KPT * 3; i += THREADS) sk[i] = K[i];
            __syncthreads();

            float acc = 0.0f;
            const float invDiv = 1.0f / (float)(BATCH * KPT * KPT);
            for (int p = tid; p < KPT * KPT; p += THREADS) {
                const int i = p >> 7;
                const int jj = p & 127;
                float c;
                if (i == jj) {
                    c = 0.1f;
                } else {
                    float dx = sk[i * 3 + 0] - sk[jj * 3 + 0];
                    float dy = sk[i * 3 + 1] - sk[jj * 3 + 1];
                    float dz = sk[i * 3 + 2] - sk[jj * 3 + 2];
                    c = fminf(sqrt_fast(fmaf(dx, dx, fmaf(dy, dy, dz * dz))), 0.1f);
                }
                acc += c * invDiv;
            }

            if (tid < KPT) {
                const float* R = gt_R + (size_t)b * 9;
                const float t0 = gt_t[b * 3 + 0], t1 = gt_t[b * 3 + 1], t2 = gt_t[b * 3 + 2];
                const float s0 = gt_s[b * 3 + 0], s1 = gt_s[b * 3 + 1], s2 = gt_s[b * 3 + 2];
                const float scale = sqrtf(s0 * s0 + s1 * s1 + s2 * s2) + 1e-8f;
                const float inv = 1.0f / scale;
                const float px = (sk[tid * 3 + 0] - t0) * inv;
                const float py = (sk[tid * 3 + 1] - t1) * inv;
                const float pz = (sk[tid * 3 + 2] - t2) * inv;
                const float* pn = pred_nocs + ((size_t)b * KPT + tid) * 3;
                float sl = 0.0f;
                #pragma unroll
                for (int jj = 0; jj < 3; jj++) {
                    float g = px * R[jj] + py * R[3 + jj] + pz * R[6 + jj];
                    float d = fabsf(pn[jj] - g);
                    sl += (d > 0.1f) ? (d - 0.05f) : (d * d * 5.0f);
                }
                acc += sl * (1.0f / (float)(BATCH * KPT));
            }

            const float* D = recon_delta + (size_t)b * NPTS * 3;
            float dsum = 0.0f;
            for (int r = tid; r < NPTS; r += THREADS) {
                float x = D[r * 3 + 0];
                float y = D[r * 3 + 1];
                float z = D[r * 3 + 2];
                dsum += sqrt_fast(fmaf(x, x, fmaf(y, y, z * z)));
            }
            acc += dsum * (1.0f / (float)(BATCH * NPTS));

            float tot = block_sum(acc, s_red);
            if (tid == 0) {
                const float* Rp = pred_R + (size_t)b * 9;
                const float* Rg = gt_R + (size_t)b * 9;
                float cs = 0.0f;
                #pragma unroll
                for (int jj = 0; jj < 3; jj++) {
                    float a0 = Rp[jj]     - Rg[jj];
                    float a1 = Rp[3 + jj] - Rg[3 + jj];
                    float a2 = Rp[6 + jj] - Rg[6 + jj];
                    cs += sqrtf(a0 * a0 + a1 * a1 + a2 * a2);
                }
                float dt0 = pred_t[b * 3 + 0] - gt_t[b * 3 + 0];
                float dt1 = pred_t[b * 3 + 1] - gt_t[b * 3 + 1];
                float dt2 = pred_t[b * 3 + 2] - gt_t[b * 3 + 2];
                float tn = sqrtf(dt0 * dt0 + dt1 * dt1 + dt2 * dt2);
                float ds0 = pred_s[b * 3 + 0] - gt_s[b * 3 + 0];
                float ds1 = pred_s[b * 3 + 1] - gt_s[b * 3 + 1];
                float ds2 = pred_s[b * 3 + 2] - gt_s[b * 3 + 2];
                float sn = sqrtf(ds0 * ds0 + ds1 * ds1 + ds2 * ds2);
                g_slots[16 + b] = tot
                                + cs * (1.0f / (3.0f * BATCH))
                                + tn * (1.0f / BATCH)
                                + sn * (1.0f / BATCH);
            }
        }
    }

    // ===== epilogue: last block finalizes =====
    __syncthreads();
    if (tid == 0) {
        __threadfence();
        s_rank = atomicAdd(&g_count, 1u);
    }
    __syncthreads();
    if (s_rank != NBLOCKS - 1u) return;

    __threadfence();
    float a = 0.0f;
    // g_min: 32768 encoded values, 128/thread as 32 coalesced uint4
    {
        float su = 0.0f;
        #pragma unroll 8
        for (int i = 0; i < 32; i++) {
            const int idx = i * 1024 + tid * 4;
            uint4 u = __ldcg((const uint4*)(g_min + idx));
            su += dec_sqrt(u.x) + dec_sqrt(u.y) + dec_sqrt(u.z) + dec_sqrt(u.w);
            *(uint4*)(g_min + idx) = make_uint4(0u, 0u, 0u, 0u);
        }
        a += su * (0.5f / (BATCH * NPTS));
    }
    // g_d3min: 1024 values, 4/thread
    {
        const int idx = tid * 4;
        uint4 u = __ldcg((const uint4*)(g_d3min + idx));
        *(uint4*)(g_d3min + idx) = make_uint4(0u, 0u, 0u, 0u);
        a += (dec_sqrt(u.x) + dec_sqrt(u.y) + dec_sqrt(u.z) + dec_sqrt(u.w))
           * (0.5f / (BATCH * KPT));
    }
    if (tid < 24) a += __ldcg(g_slots + tid);

    float tot = block_sum(a, s_red);
    if (tid == 0) {
        out[0] = tot;
        g_count = 0;  // reset for graph replay
    }
}

extern "C" void kernel_launch(void* const* d_in, const int* in_sizes, int n_in,
                              void* d_out, int out_size) {
    const float* pts         = (const float*)d_in[0];
    const float* recon_delta = (const float*)d_in[1];
    const float* kpt         = (const float*)d_in[2];
    const float* recon       = (const float*)d_in[3];
    const float* pred_nocs   = (const float*)d_in[4];
    const float* pred_R      = (const float*)d_in[5];
    const float* pred_t      = (const float*)d_in[6];
    const float* pred_s      = (const float*)d_in[7];
    const float* gt_R        = (const float*)d_in[8];
    const float* gt_t        = (const float*)d_in[9];
    const float* gt_s        = (const float*)d_in[10];

    fused<<<NBLOCKS, THREADS>>>(pts, recon, kpt, recon_delta, pred_nocs,
                                pred_R, pred_t, pred_s, gt_R, gt_t, gt_s,
                                (float*)d_out);
}

// round 13
// speedup vs baseline: 1.0817x; 1.0817x over previous
#include <cuda_runtime.h>
#include <math.h>

#define BATCH 8
#define NPTS 2048
#define KPT 128
#define THREADS 256
#define SLEN 64
#define NBLOCKS 568

// Encoded min-d^2 accumulators. u = ~__float_as_uint(max(d2,0)).
// Monotone-decreasing encoding: unsigned atomicMax == float min.
// All encoded values >= 0x80000000, so zero (initial / post-finalize reset)
// is the identity.
// [0..16384): per-pts-row min (pts -> recon);  [16384..32768): per-recon min.
__device__ unsigned int g_min[2 * 16384];
__device__ unsigned int g_d3min[1024];      // [b*128 + r]
// slots: [0..15] dir2 item sums, [16..23] per-batch small losses
__device__ float g_slots[24];
__device__ unsigned int g_count;

__device__ __forceinline__ unsigned int enc_min(float d2) {
    return ~__float_as_uint(fmaxf(d2, 0.0f));
}
__device__ __forceinline__ float dec_sqrt(unsigned int u) {
    float x = __uint_as_float(~u);
    float r;
    asm("sqrt.approx.f32 %0, %1;" : "=f"(r) : "f"(x));
    return r;
}
__device__ __forceinline__ float sqrt_fast(float x) {
    float r;
    asm("sqrt.approx.f32 %0, %1;" : "=f"(r) : "f"(x));
    return r;
}

// block sum over 256 threads; result valid on tid 0.
__device__ __forceinline__ float block_sum(float v, float* red8) {
    const int tid = threadIdx.x;
    #pragma unroll
    for (int o = 16; o > 0; o >>= 1) v += __shfl_down_sync(0xFFFFFFFFu, v, o);
    if ((tid & 31) == 0) red8[tid >> 5] = v;
    __syncthreads();
    if (tid < 8) {
        v = red8[tid];
        #pragma unroll
        for (int o = 4; o > 0; o >>= 1) v += __shfl_down_sync(0xFFu, v, o);
    }
    return v;
}

__global__ void __launch_bounds__(THREADS, 4)
fused(const float* __restrict__ pts,
      const float* __restrict__ recon,
      const float* __restrict__ kpt,
      const float* __restrict__ recon_delta,
      const float* __restrict__ pred_nocs,
      const float* __restrict__ pred_R,
      const float* __restrict__ pred_t,
      const float* __restrict__ pred_s,
      const float* __restrict__ gt_R,
      const float* __restrict__ gt_t,
      const float* __restrict__ gt_s,
      float* __restrict__ out) {
    __shared__ __align__(16) unsigned char s_buf[8192];
    __shared__ float s_red[8];
    __shared__ unsigned int s_rank;

    const int bid = blockIdx.x;
    const int tid = threadIdx.x;

    if (bid < 512) {
        // ===== heavy: pts x recon tile, 1024 rows x 64 cols, BOTH directions =====
        const int b  = bid >> 6;
        const int rh = (bid >> 5) & 1;   // row half
        const int sl = bid & 31;         // 64-col slice

        const float* Q = pts   + ((size_t)b * NPTS + rh * 1024) * 3;
        const float* T = recon + ((size_t)b * NPTS + sl * SLEN) * 3;

        float4* tile = (float4*)s_buf;                     // 64 x 16B
        volatile float* cmin = (float*)(s_buf + 1024);     // 8 warps x 64 cols

        if (tid < SLEN) {
            float x = T[tid * 3 + 0];
            float y = T[tid * 3 + 1];
            float z = T[tid * 3 + 2];
            float w = fmaf(x, x, fmaf(y, y, z * z));
            tile[tid] = make_float4(-2.0f * x, -2.0f * y, -2.0f * z, w);
        }
        cmin[tid] = 3.0e38f;
        cmin[tid + 256] = 3.0e38f;
        __syncthreads();

        // 4 query rows per thread
        float qx[4], qy[4], qz[4], qq[4];
        #pragma unroll
        for (int q = 0; q < 4; q++) {
            const int r = tid + 256 * q;
            qx[q] = Q[r * 3 + 0];
            qy[q] = Q[r * 3 + 1];
            qz[q] = Q[r * 3 + 2];
            qq[q] = fmaf(qx[q], qx[q], fmaf(qy[q], qy[q], qz[q] * qz[q]));
        }

        float m[4];
        #pragma unroll
        for (int q = 0; q < 4; q++) m[q] = 3.0e38f;

        volatile float* cm = cmin + (tid >> 5) * 64;  // per-warp col-min array
        const int cbase = tid & 63;

        #pragma unroll 4
        for (int k = 0; k < SLEN; k++) {
            const int c = cbase ^ k;      // lanes in a warp hit distinct cols
            const float4 sv = tile[c];
            // full d^2 = q^2 - 2 q.s + s^2
            float v0 = fmaf(sv.x, qx[0], fmaf(sv.y, qy[0], fmaf(sv.z, qz[0], qq[0]))) + sv.w;
            float v1 = fmaf(sv.x, qx[1], fmaf(sv.y, qy[1], fmaf(sv.z, qz[1], qq[1]))) + sv.w;
            float v2 = fmaf(sv.x, qx[2], fmaf(sv.y, qy[2], fmaf(sv.z, qz[2], qq[2]))) + sv.w;
            float v3 = fmaf(sv.x, qx[3], fmaf(sv.y, qy[3], fmaf(sv.z, qz[3], qq[3]))) + sv.w;
            m[0] = fminf(m[0], v0);
            m[1] = fminf(m[1], v1);
            m[2] = fminf(m[2], v2);
            m[3] = fminf(m[3], v3);
            float tv = fminf(fminf(v0, v1), fminf(v2, v3));
            cm[c] = fminf(cm[c], tv);
        }

        // row mins (pts -> recon direction)
        unsigned int* dst = g_min + b * 2048 + rh * 1024;
        #pragma unroll
        for (int q = 0; q < 4; q++)
            atomicMax(&dst[tid + 256 * q], enc_min(m[q]));

        __syncthreads();
        // column mins (recon -> pts direction): merge 8 warp arrays
        if (tid < SLEN) {
            float mc = cmin[tid];
            #pragma unroll
            for (int w = 1; w < 8; w++) mc = fminf(mc, cmin[w * 64 + tid]);
            atomicMax(&g_min[16384 + b * 2048 + sl * SLEN + tid], enc_min(mc));
        }
    } else {
        const int id = bid - 512;
        if (id < 16) {
            // dir2: pts -> kpt, 1024-row half, full 128 targets (direct sum)
            const int b = id >> 1;
            const int half = id & 1;
            const float* Q = pts + (size_t)b * NPTS * 3;
            const float* T = kpt + (size_t)b * KPT * 3;
            float4* tile = (float4*)s_buf;
            if (tid < KPT) {
                float x = T[tid * 3 + 0];
                float y = T[tid * 3 + 1];
                float z = T[tid * 3 + 2];
                float w = fmaf(x, x, fmaf(y, y, z * z));
                tile[tid] = make_float4(-2.0f * x, -2.0f * y, -2.0f * z, w);
            }
            __syncthreads();

            const int rowbase = half * 1024;
            float sum = 0.0f;
            #pragma unroll
            for (int q = 0; q < 4; q++) {
                const int r = rowbase + tid + 256 * q;
                float qx = Q[r * 3 + 0];
                float qy = Q[r * 3 + 1];
                float qz = Q[r * 3 + 2];
                float q2 = fmaf(qx, qx, fmaf(qy, qy, qz * qz));
                float mm = 3.0e38f;
                #pragma unroll 8
                for (int t = 0; t < KPT; t++) {
                    float4 sv = tile[t];
                    float v = fmaf(sv.x, qx, fmaf(sv.y, qy, fmaf(sv.z, qz, sv.w)));
                    mm = fminf(mm, v);
                }
                sum += sqrt_fast(fmaxf(q2 + mm, 0.0f));
            }
            float tot = block_sum(sum, s_red);
            if (tid == 0) g_slots[id] = tot * (0.5f / (BATCH * NPTS));
        } else if (id < 48) {
            // dir3: kpt -> pts, 512-target quarter -> atomic min partial
            const int j = id - 16;
            const int b = j >> 2;
            const int quarter = j & 3;
            const float* Q = kpt + (size_t)b * KPT * 3;
            const float* T = pts + (size_t)b * NPTS * 3 + quarter * 512 * 3;
            float4* tile = (float4*)s_buf;
            for (int jj = tid; jj < 512; jj += THREADS) {
                float x = T[jj * 3 + 0];
                float y = T[jj * 3 + 1];
                float z = T[jj * 3 + 2];
                float w = fmaf(x, x, fmaf(y, y, z * z));
                tile[jj] = make_float4(-2.0f * x, -2.0f * y, -2.0f * z, w);
            }
            __syncthreads();

            if (tid < KPT) {
                float qx = Q[tid * 3 + 0];
                float qy = Q[tid * 3 + 1];
                float qz = Q[tid * 3 + 2];
                float q2 = fmaf(qx, qx, fmaf(qy, qy, qz * qz));
                float mm = 3.0e38f;
                #pragma unroll 8
                for (int t = 0; t < 512; t++) {
                    float4 sv = tile[t];
                    float v = fmaf(sv.x, qx, fmaf(sv.y, qy, fmaf(sv.z, qz, sv.w)));
                    mm = fminf(mm, v);
                }
                atomicMax(&g_d3min[b * KPT + tid], enc_min(q2 + mm));
            }
        } else {
            // smalls: pose + NOCS + diversity + delta per batch
            const int b = id - 48;
            float* sk = (float*)s_buf;
            const float* K = kpt + (size_t)b * KPT * 3;
            for (int i = tid; i < KPT * 3; i += THREADS) sk[i] = K[i];
            __syncthreads();

            float acc = 0.0f;
            const float invDiv = 1.0f / (float)(BATCH * KPT * KPT);
            for (int p = tid; p < KPT * KPT; p += THREADS) {
                const int i = p >> 7;
                const int jj = p & 127;
                float c;
                if (i == jj) {
                    c = 0.1f;
                } else {
                    float dx = sk[i * 3 + 0] - sk[jj * 3 + 0];
                    float dy = sk[i * 3 + 1] - sk[jj * 3 + 1];
                    float dz = sk[i * 3 + 2] - sk[jj * 3 + 2];
                    c = fminf(sqrt_fast(fmaf(dx, dx, fmaf(dy, dy, dz * dz))), 0.1f);
                }
                acc += c * invDiv;
            }

            if (tid < KPT) {
                const float* R = gt_R + (size_t)b * 9;
                const float t0 = gt_t[b * 3 + 0], t1 = gt_t[b * 3 + 1], t2 = gt_t[b * 3 + 2];
                const float s0 = gt_s[b * 3 + 0], s1 = gt_s[b * 3 + 1], s2 = gt_s[b * 3 + 2];
                const float scale = sqrtf(s0 * s0 + s1 * s1 + s2 * s2) + 1e-8f;
                const float inv = 1.0f / scale;
                const float px = (sk[tid * 3 + 0] - t0) * inv;
                const float py = (sk[tid * 3 + 1] - t1) * inv;
                const float pz = (sk[tid * 3 + 2] - t2) * inv;
                const float* pn = pred_nocs + ((size_t)b * KPT + tid) * 3;
                float sl = 0.0f;
                #pragma unroll
                for (int jj = 0; jj < 3; jj++) {
                    float g = px * R[jj] + py * R[3 + jj] + pz * R[6 + jj];
                    float d = fabsf(pn[jj] - g);
                    sl += (d > 0.1f) ? (d - 0.05f) : (d * d * 5.0f);
                }
                acc += sl * (1.0f / (float)(BATCH * KPT));
            }

            const float* D = recon_delta + (size_t)b * NPTS * 3;
            float dsum = 0.0f;
            for (int r = tid; r < NPTS; r += THREADS) {
                float x = D[r * 3 + 0];
                float y = D[r * 3 + 1];
                float z = D[r * 3 + 2];
                dsum += sqrt_fast(fmaf(x, x, fmaf(y, y, z * z)));
            }
            acc += dsum * (1.0f / (float)(BATCH * NPTS));

            float tot = block_sum(acc, s_red);
            if (tid == 0) {
                const float* Rp = pred_R + (size_t)b * 9;
                const float* Rg = gt_R + (size_t)b * 9;
                float cs = 0.0f;
                #pragma unroll
                for (int jj = 0; jj < 3; jj++) {
                    float a0 = Rp[jj]     - Rg[jj];
                    float a1 = Rp[3 + jj] - Rg[3 + jj];
                    float a2 = Rp[6 + jj] - Rg[6 + jj];
                    cs += sqrtf(a0 * a0 + a1 * a1 + a2 * a2);
                }
                float dt0 = pred_t[b * 3 + 0] - gt_t[b * 3 + 0];
                float dt1 = pred_t[b * 3 + 1] - gt_t[b * 3 + 1];
                float dt2 = pred_t[b * 3 + 2] - gt_t[b * 3 + 2];
                float tn = sqrtf(dt0 * dt0 + dt1 * dt1 + dt2 * dt2);
                float ds0 = pred_s[b * 3 + 0] - gt_s[b * 3 + 0];
                float ds1 = pred_s[b * 3 + 1] - gt_s[b * 3 + 1];
                float ds2 = pred_s[b * 3 + 2] - gt_s[b * 3 + 2];
                float sn = sqrtf(ds0 * ds0 + ds1 * ds1 + ds2 * ds2);
                g_slots[16 + b] = tot
                                + cs * (1.0f / (3.0f * BATCH))
                                + tn * (1.0f / BATCH)
                                + sn * (1.0f / BATCH);
            }
        }
    }

    // ===== epilogue: last block finalizes =====
    __syncthreads();
    if (tid == 0) {
        __threadfence();
        s_rank = atomicAdd(&g_count, 1u);
    }
    __syncthreads();
    if (s_rank != NBLOCKS - 1u) return;

    __threadfence();
    float a = 0.0f;
    {
        float su = 0.0f;
        #pragma unroll 8
        for (int i = 0; i < 32; i++) {
            const int idx = i * 1024 + tid * 4;
            uint4 u = __ldcg((const uint4*)(g_min + idx));
            su += dec_sqrt(u.x) + dec_sqrt(u.y) + dec_sqrt(u.z) + dec_sqrt(u.w);
            *(uint4*)(g_min + idx) = make_uint4(0u, 0u, 0u, 0u);
        }
        a += su * (0.5f / (BATCH * NPTS));
    }
    {
        const int idx = tid * 4;
        uint4 u = __ldcg((const uint4*)(g_d3min + idx));
        *(uint4*)(g_d3min + idx) = make_uint4(0u, 0u, 0u, 0u);
        a += (dec_sqrt(u.x) + dec_sqrt(u.y) + dec_sqrt(u.z) + dec_sqrt(u.w))
           * (0.5f / (BATCH * KPT));
    }
    if (tid < 24) a += __ldcg(g_slots + tid);

    float tot = block_sum(a, s_red);
    if (tid == 0) {
        out[0] = tot;
        g_count = 0;  // reset for graph replay
    }
}

extern "C" void kernel_launch(void* const* d_in, const int* in_sizes, int n_in,
                              void* d_out, int out_size) {
    const float* pts         = (const float*)d_in[0];
    const float* recon_delta = (const float*)d_in[1];
    const float* kpt         = (const float*)d_in[2];
    const float* recon       = (const float*)d_in[3];
    const float* pred_nocs   = (const float*)d_in[4];
    const float* pred_R      = (const float*)d_in[5];
    const float* pred_t      = (const float*)d_in[6];
    const float* pred_s      = (const float*)d_in[7];
    const float* gt_R        = (const float*)d_in[8];
    const float* gt_t        = (const float*)d_in[9];
    const float* gt_s        = (const float*)d_in[10];

    fused<<<NBLOCKS, THREADS>>>(pts, recon, kpt, recon_delta, pred_nocs,
                                pred_R, pred_t, pred_s, gt_R, gt_t, gt_s,
                                (float*)d_out);
}

// round 14
// speedup vs baseline: 1.1635x; 1.0755x over previous
#include <cuda_runtime.h>
#include <math.h>

#define BATCH 8
#define NPTS 2048
#define KPT 128
#define THREADS 256
#define SLEN 64
#define NBLOCKS 568

// Encoded min-d^2 accumulators. u = ~__float_as_uint(max(d2,0)).
// Monotone-decreasing encoding: unsigned atomicMax == float min.
// All encoded values >= 0x80000000, so zero (initial / post-finalize reset)
// is the identity.
// [0..16384): per-pts-row min (pts -> recon);  [16384..32768): per-recon min.
__device__ unsigned int g_min[2 * 16384];
__device__ unsigned int g_d3min[1024];      // [b*128 + r]
// slots: [0..15] dir2 item sums, [16..23] per-batch small losses
__device__ float g_slots[24];
// group sums: [0..15] row groups (b*2+rh), [16..23] col groups (b), [24] dir3
__device__ float g_gsum[25];
__device__ unsigned int g_cnt_row[16];
__device__ unsigned int g_cnt_col[8];
__device__ unsigned int g_cnt_d3;
__device__ unsigned int g_count;

__device__ __forceinline__ unsigned int enc_min(float d2) {
    return ~__float_as_uint(fmaxf(d2, 0.0f));
}
__device__ __forceinline__ float dec_sqrt(unsigned int u) {
    float x = __uint_as_float(~u);
    float r;
    asm("sqrt.approx.f32 %0, %1;" : "=f"(r) : "f"(x));
    return r;
}
__device__ __forceinline__ float sqrt_fast(float x) {
    float r;
    asm("sqrt.approx.f32 %0, %1;" : "=f"(r) : "f"(x));
    return r;
}

// block sum over 256 threads; result valid on tid 0. Safe for repeated calls
// (leading barrier isolates s_red reuse).
__device__ __forceinline__ float block_sum(float v, float* red8) {
    const int tid = threadIdx.x;
    __syncthreads();
    #pragma unroll
    for (int o = 16; o > 0; o >>= 1) v += __shfl_down_sync(0xFFFFFFFFu, v, o);
    if ((tid & 31) == 0) red8[tid >> 5] = v;
    __syncthreads();
    if (tid < 8) {
        v = red8[tid];
        #pragma unroll
        for (int o = 4; o > 0; o >>= 1) v += __shfl_down_sync(0xFFu, v, o);
    }
    return v;
}

__global__ void __launch_bounds__(THREADS, 4)
fused(const float* __restrict__ pts,
      const float* __restrict__ recon,
      const float* __restrict__ kpt,
      const float* __restrict__ recon_delta,
      const float* __restrict__ pred_nocs,
      const float* __restrict__ pred_R,
      const float* __restrict__ pred_t,
      const float* __restrict__ pred_s,
      const float* __restrict__ gt_R,
      const float* __restrict__ gt_t,
      const float* __restrict__ gt_s,
      float* __restrict__ out) {
    __shared__ __align__(16) unsigned char s_buf[8192];
    __shared__ float s_red[8];
    __shared__ unsigned int s_rank, s_g1, s_g2;

    const int bid = blockIdx.x;
    const int tid = threadIdx.x;

    if (bid < 512) {
        // ===== heavy: pts x recon tile, 1024 rows x 64 cols, BOTH directions =====
        const int b  = bid >> 6;
        const int rh = (bid >> 5) & 1;   // row half
        const int sl = bid & 31;         // 64-col slice

        const float* Q = pts   + ((size_t)b * NPTS + rh * 1024) * 3;
        const float* T = recon + ((size_t)b * NPTS + sl * SLEN) * 3;

        float4* tile = (float4*)s_buf;                     // 64 x 16B
        volatile float* cmin = (float*)(s_buf + 1024);     // 8 warps x 64 cols

        if (tid < SLEN) {
            float x = T[tid * 3 + 0];
            float y = T[tid * 3 + 1];
            float z = T[tid * 3 + 2];
            float w = fmaf(x, x, fmaf(y, y, z * z));
            tile[tid] = make_float4(-2.0f * x, -2.0f * y, -2.0f * z, w);
        }
        cmin[tid] = 3.0e38f;
        cmin[tid + 256] = 3.0e38f;
        __syncthreads();

        float qx[4], qy[4], qz[4], qq[4];
        #pragma unroll
        for (int q = 0; q < 4; q++) {
            const int r = tid + 256 * q;
            qx[q] = Q[r * 3 + 0];
            qy[q] = Q[r * 3 + 1];
            qz[q] = Q[r * 3 + 2];
            qq[q] = fmaf(qx[q], qx[q], fmaf(qy[q], qy[q], qz[q] * qz[q]));
        }

        float m[4];
        #pragma unroll
        for (int q = 0; q < 4; q++) m[q] = 3.0e38f;

        volatile float* cm = cmin + (tid >> 5) * 64;
        const int cbase = tid & 63;

        #pragma unroll 4
        for (int k = 0; k < SLEN; k++) {
            const int c = cbase ^ k;      // lanes in a warp hit distinct cols
            const float4 sv = tile[c];
            float v0 = fmaf(sv.x, qx[0], fmaf(sv.y, qy[0], fmaf(sv.z, qz[0], qq[0]))) + sv.w;
            float v1 = fmaf(sv.x, qx[1], fmaf(sv.y, qy[1], fmaf(sv.z, qz[1], qq[1]))) + sv.w;
            float v2 = fmaf(sv.x, qx[2], fmaf(sv.y, qy[2], fmaf(sv.z, qz[2], qq[2]))) + sv.w;
            float v3 = fmaf(sv.x, qx[3], fmaf(sv.y, qy[3], fmaf(sv.z, qz[3], qq[3]))) + sv.w;
            m[0] = fminf(m[0], v0);
            m[1] = fminf(m[1], v1);
            m[2] = fminf(m[2], v2);
            m[3] = fminf(m[3], v3);
            float tv = fminf(fminf(v0, v1), fminf(v2, v3));
            cm[c] = fminf(cm[c], tv);
        }

        unsigned int* dst = g_min + b * 2048 + rh * 1024;
        #pragma unroll
        for (int q = 0; q < 4; q++)
            atomicMax(&dst[tid + 256 * q], enc_min(m[q]));

        __syncthreads();
        if (tid < SLEN) {
            float mc = cmin[tid];
            #pragma unroll
            for (int w = 1; w < 8; w++) mc = fminf(mc, cmin[w * 64 + tid]);
            atomicMax(&g_min[16384 + b * 2048 + sl * SLEN + tid], enc_min(mc));
        }

        // ---- group finalize ----
        __threadfence();
        if (tid == 0) {
            s_g1 = atomicAdd(&g_cnt_row[b * 2 + rh], 1u);
            s_g2 = atomicAdd(&g_cnt_col[b], 1u);
        }
        __syncthreads();

        if (s_g1 == 31u) {  // last slice for this row group: decode 1024 rows
            __threadfence();
            const int base = b * 2048 + rh * 1024 + tid * 4;
            uint4 u = __ldcg((const uint4*)(g_min + base));
            *(uint4*)(g_min + base) = make_uint4(0u, 0u, 0u, 0u);
            float su = dec_sqrt(u.x) + dec_sqrt(u.y) + dec_sqrt(u.z) + dec_sqrt(u.w);
            float tot = block_sum(su, s_red);
            if (tid == 0) {
                g_gsum[b * 2 + rh] = tot * (0.5f / (BATCH * NPTS));
                g_cnt_row[b * 2 + rh] = 0u;
            }
        }
        if (s_g2 == 63u) {  // last block for this batch: decode 2048 cols
            __threadfence();
            float su = 0.0f;
            #pragma unroll
            for (int i = 0; i < 2; i++) {
                const int base = 16384 + b * 2048 + i * 1024 + tid * 4;
                uint4 u = __ldcg((const uint4*)(g_min + base));
                *(uint4*)(g_min + base) = make_uint4(0u, 0u, 0u, 0u);
                su += dec_sqrt(u.x) + dec_sqrt(u.y) + dec_sqrt(u.z) + dec_sqrt(u.w);
            }
            float tot = block_sum(su, s_red);
            if (tid == 0) {
                g_gsum[16 + b] = tot * (0.5f / (BATCH * NPTS));
                g_cnt_col[b] = 0u;
            }
        }
    } else {
        const int id = bid - 512;
        if (id < 16) {
            // dir2: pts -> kpt, 1024-row half, full 128 targets (direct sum)
            const int b = id >> 1;
            const int half = id & 1;
            const float* Q = pts + (size_t)b * NPTS * 3;
            const float* T = kpt + (size_t)b * KPT * 3;
            float4* tile = (float4*)s_buf;
            if (tid < KPT) {
                float x = T[tid * 3 + 0];
                float y = T[tid * 3 + 1];
                float z = T[tid * 3 + 2];
                float w = fmaf(x, x, fmaf(y, y, z * z));
                tile[tid] = make_float4(-2.0f * x, -2.0f * y, -2.0f * z, w);
            }
            __syncthreads();

            const int rowbase = half * 1024;
            float sum = 0.0f;
            #pragma unroll
            for (int q = 0; q < 4; q++) {
                const int r = rowbase + tid + 256 * q;
                float qx = Q[r * 3 + 0];
                float qy = Q[r * 3 + 1];
                float qz = Q[r * 3 + 2];
                float q2 = fmaf(qx, qx, fmaf(qy, qy, qz * qz));
                float mm = 3.0e38f;
                #pragma unroll 8
                for (int t = 0; t < KPT; t++) {
                    float4 sv = tile[t];
                    float v = fmaf(sv.x, qx, fmaf(sv.y, qy, fmaf(sv.z, qz, sv.w)));
                    mm = fminf(mm, v);
                }
                sum += sqrt_fast(fmaxf(q2 + mm, 0.0f));
            }
            float tot = block_sum(sum, s_red);
            if (tid == 0) g_slots[id] = tot * (0.5f / (BATCH * NPTS));
        } else if (id < 48) {
            // dir3: kpt -> pts, 512-target quarter -> atomic min partial
            const int j = id - 16;
            const int b = j >> 2;
            const int quarter = j & 3;
            const float* Q = kpt + (size_t)b * KPT * 3;
            const float* T = pts + (size_t)b * NPTS * 3 + quarter * 512 * 3;
            float4* tile = (float4*)s_buf;
            for (int jj = tid; jj < 512; jj += THREADS) {
                float x = T[jj * 3 + 0];
                float y = T[jj * 3 + 1];
                float z = T[jj * 3 + 2];
                float w = fmaf(x, x, fmaf(y, y, z * z));
                tile[jj] = make_float4(-2.0f * x, -2.0f * y, -2.0f * z, w);
            }
            __syncthreads();

            if (tid < KPT) {
                float qx = Q[tid * 3 + 0];
                float qy = Q[tid * 3 + 1];
                float qz = Q[tid * 3 + 2];
                float q2 = fmaf(qx, qx, fmaf(qy, qy, qz * qz));
                float mm = 3.0e38f;
                #pragma unroll 8
                for (int t = 0; t < 512; t++) {
                    float4 sv = tile[t];
                    float v = fmaf(sv.x, qx, fmaf(sv.y, qy, fmaf(sv.z, qz, sv.w)));
                    mm = fminf(mm, v);
                }
                atomicMax(&g_d3min[b * KPT + tid], enc_min(q2 + mm));
            }

            // ---- dir3 group finalize ----
            __threadfence();
            if (tid == 0) s_g1 = atomicAdd(&g_cnt_d3, 1u);
            __syncthreads();
            if (s_g1 == 31u) {
                __threadfence();
                const int base = tid * 4;
                uint4 u = __ldcg((const uint4*)(g_d3min + base));
                *(uint4*)(g_d3min + base) = make_uint4(0u, 0u, 0u, 0u);
                float su = dec_sqrt(u.x) + dec_sqrt(u.y) + dec_sqrt(u.z) + dec_sqrt(u.w);
                float tot = block_sum(su, s_red);
                if (tid == 0) {
                    g_gsum[24] = tot * (0.5f / (BATCH * KPT));
                    g_cnt_d3 = 0u;
                }
            }
        } else {
            // smalls: pose + NOCS + diversity + delta per batch
            const int b = id - 48;
            float* sk = (float*)s_buf;
            const float* K = kpt + (size_t)b * KPT * 3;
            for (int i = tid; i < KPT * 3; i += THREADS) sk[i] = K[i];
            __syncthreads();

            float acc = 0.0f;
            const float invDiv = 1.0f / (float)(BATCH * KPT * KPT);
            for (int p = tid; p < KPT * KPT; p += THREADS) {
                const int i = p >> 7;
                const int jj = p & 127;
                float c;
                if (i == jj) {
                    c = 0.1f;
                } else {
                    float dx = sk[i * 3 + 0] - sk[jj * 3 + 0];
                    float dy = sk[i * 3 + 1] - sk[jj * 3 + 1];
                    float dz = sk[i * 3 + 2] - sk[jj * 3 + 2];
                    c = fminf(sqrt_fast(fmaf(dx, dx, fmaf(dy, dy, dz * dz))), 0.1f);
                }
                acc += c * invDiv;
            }

            if (tid < KPT) {
                const float* R = gt_R + (size_t)b * 9;
                const float t0 = gt_t[b * 3 + 0], t1 = gt_t[b * 3 + 1], t2 = gt_t[b * 3 + 2];
                const float s0 = gt_s[b * 3 + 0], s1 = gt_s[b * 3 + 1], s2 = gt_s[b * 3 + 2];
                const float scale = sqrtf(s0 * s0 + s1 * s1 + s2 * s2) + 1e-8f;
                const float inv = 1.0f / scale;
                const float px = (sk[tid * 3 + 0] - t0) * inv;
                const float py = (sk[tid * 3 + 1] - t1) * inv;
                const float pz = (sk[tid * 3 + 2] - t2) * inv;
                const float* pn = pred_nocs + ((size_t)b * KPT + tid) * 3;
                float sl = 0.0f;
                #pragma unroll
                for (int jj = 0; jj < 3; jj++) {
                    float g = px * R[jj] + py * R[3 + jj] + pz * R[6 + jj];
                    float d = fabsf(pn[jj] - g);
                    sl += (d > 0.1f) ? (d - 0.05f) : (d * d * 5.0f);
                }
                acc += sl * (1.0f / (float)(BATCH * KPT));
            }

            const float* D = recon_delta + (size_t)b * NPTS * 3;
            float dsum = 0.0f;
            for (int r = tid; r < NPTS; r += THREADS) {
                float x = D[r * 3 + 0];
                float y = D[r * 3 + 1];
                float z = D[r * 3 + 2];
                dsum += sqrt_fast(fmaf(x, x, fmaf(y, y, z * z)));
            }
            acc += dsum * (1.0f / (float)(BATCH * NPTS));

            float tot = block_sum(acc, s_red);
            if (tid == 0) {
                const float* Rp = pred_R + (size_t)b * 9;
                const float* Rg = gt_R + (size_t)b * 9;
                float cs = 0.0f;
                #pragma unroll
                for (int jj = 0; jj < 3; jj++) {
                    float a0 = Rp[jj]     - Rg[jj];
                    float a1 = Rp[3 + jj] - Rg[3 + jj];
                    float a2 = Rp[6 + jj] - Rg[6 + jj];
                    cs += sqrtf(a0 * a0 + a1 * a1 + a2 * a2);
                }
                float dt0 = pred_t[b * 3 + 0] - gt_t[b * 3 + 0];
                float dt1 = pred_t[b * 3 + 1] - gt_t[b * 3 + 1];
                float dt2 = pred_t[b * 3 + 2] - gt_t[b * 3 + 2];
                float tn = sqrtf(dt0 * dt0 + dt1 * dt1 + dt2 * dt2);
                float ds0 = pred_s[b * 3 + 0] - gt_s[b * 3 + 0];
                float ds1 = pred_s[b * 3 + 1] - gt_s[b * 3 + 1];
                float ds2 = pred_s[b * 3 + 2] - gt_s[b * 3 + 2];
                float sn = sqrtf(ds0 * ds0 + ds1 * ds1 + ds2 * ds2);
                g_slots[16 + b] = tot
                                + cs * (1.0f / (3.0f * BATCH))
                                + tn * (1.0f / BATCH)
                                + sn * (1.0f / BATCH);
            }
        }
    }

    // ===== global epilogue: last block sums 49 scalars =====
    __syncthreads();
    if (tid == 0) {
        __threadfence();
        s_rank = atomicAdd(&g_count, 1u);
    }
    __syncthreads();
    if (s_rank != NBLOCKS - 1u) return;

    __threadfence();
    float a = 0.0f;
    if (tid < 25) a += __ldcg(g_gsum + tid);
    if (tid >= 32 && tid < 56) a += __ldcg(g_slots + (tid - 32));

    float tot = block_sum(a, s_red);
    if (tid == 0) {
        out[0] = tot;
        g_count = 0;  // reset for graph replay
    }
}

extern "C" void kernel_launch(void* const* d_in, const int* in_sizes, int n_in,
                              void* d_out, int out_size) {
    const float* pts         = (const float*)d_in[0];
    const float* recon_delta = (const float*)d_in[1];
    const float* kpt         = (const float*)d_in[2];
    const float* recon       = (const float*)d_in[3];
    const float* pred_nocs   = (const float*)d_in[4];
    const float* pred_R      = (const float*)d_in[5];
    const float* pred_t      = (const float*)d_in[6];
    const float* pred_s      = (const float*)d_in[7];
    const float* gt_R        = (const float*)d_in[8];
    const float* gt_t        = (const float*)d_in[9];
    const float* gt_s        = (const float*)d_in[10];

    fused<<<NBLOCKS, THREADS>>>(pts, recon, kpt, recon_delta, pred_nocs,
                                pred_R, pred_t, pred_s, gt_R, gt_t, gt_s,
                                (float*)d_out);
}

// round 15
// speedup vs baseline: 1.1780x; 1.0125x over previous
#include <cuda_runtime.h>
#include <math.h>

#define BATCH 8
#define NPTS 2048
#define KPT 128
#define THREADS 256
#define SLEN 64
#define NBLOCKS 584

// Encoded min-d^2 accumulators. u = ~__float_as_uint(max(d2,0)).
// Monotone-decreasing encoding: unsigned atomicMax == float min.
// All encoded values >= 0x80000000, so zero (initial / post-finalize reset)
// is the identity.
// [0..16384): per-pts-row min (pts -> recon);  [16384..32768): per-recon min.
__device__ unsigned int g_min[2 * 16384];
__device__ unsigned int g_d3min[1024];      // [b*128 + r]
// slots: [0..31] dir2 item sums, [32..39] per-batch small losses
__device__ float g_slots[40];
// group sums: [0..15] row groups (b*2+rh), [16..23] col groups (b), [24] dir3
__device__ float g_gsum[25];
__device__ unsigned int g_cnt_row[16];
__device__ unsigned int g_cnt_col[8];
__device__ unsigned int g_cnt_d3;
__device__ unsigned int g_count;

__device__ __forceinline__ unsigned int enc_min(float d2) {
    return ~__float_as_uint(fmaxf(d2, 0.0f));
}
__device__ __forceinline__ float dec_sqrt(unsigned int u) {
    float x = __uint_as_float(~u);
    float r;
    asm("sqrt.approx.f32 %0, %1;" : "=f"(r) : "f"(x));
    return r;
}
__device__ __forceinline__ float sqrt_fast(float x) {
    float r;
    asm("sqrt.approx.f32 %0, %1;" : "=f"(r) : "f"(x));
    return r;
}

// block sum over 256 threads; result valid on tid 0. Safe for repeated calls
// (leading barrier isolates s_red reuse).
__device__ __forceinline__ float block_sum(float v, float* red8) {
    const int tid = threadIdx.x;
    __syncthreads();
    #pragma unroll
    for (int o = 16; o > 0; o >>= 1) v += __shfl_down_sync(0xFFFFFFFFu, v, o);
    if ((tid & 31) == 0) red8[tid >> 5] = v;
    __syncthreads();
    if (tid < 8) {
        v = red8[tid];
        #pragma unroll
        for (int o = 4; o > 0; o >>= 1) v += __shfl_down_sync(0xFFu, v, o);
    }
    return v;
}

__global__ void __launch_bounds__(THREADS, 4)
fused(const float* __restrict__ pts,
      const float* __restrict__ recon,
      const float* __restrict__ kpt,
      const float* __restrict__ recon_delta,
      const float* __restrict__ pred_nocs,
      const float* __restrict__ pred_R,
      const float* __restrict__ pred_t,
      const float* __restrict__ pred_s,
      const float* __restrict__ gt_R,
      const float* __restrict__ gt_t,
      const float* __restrict__ gt_s,
      float* __restrict__ out) {
    __shared__ __align__(16) unsigned char s_buf[8192];
    __shared__ float s_red[8];
    __shared__ unsigned int s_rank, s_g1, s_g2;

    const int bid = blockIdx.x;
    const int tid = threadIdx.x;

    if (bid < 512) {
        // ===== heavy: pts x recon tile, 1024 rows x 64 cols, BOTH directions =====
        const int b  = bid >> 6;
        const int rh = (bid >> 5) & 1;   // row half
        const int sl = bid & 31;         // 64-col slice

        const float* Q = pts   + ((size_t)b * NPTS + rh * 1024) * 3;
        const float* T = recon + ((size_t)b * NPTS + sl * SLEN) * 3;

        float4* tile = (float4*)s_buf;                     // 64 x 16B
        volatile float* cmin = (float*)(s_buf + 1024);     // 8 warps x 64 cols

        if (tid < SLEN) {
            float x = T[tid * 3 + 0];
            float y = T[tid * 3 + 1];
            float z = T[tid * 3 + 2];
            float w = fmaf(x, x, fmaf(y, y, z * z));
            tile[tid] = make_float4(-2.0f * x, -2.0f * y, -2.0f * z, w);
        }
        cmin[tid] = 3.0e38f;
        cmin[tid + 256] = 3.0e38f;
        __syncthreads();

        float qx[4], qy[4], qz[4], qq[4];
        #pragma unroll
        for (int q = 0; q < 4; q++) {
            const int r = tid + 256 * q;
            qx[q] = Q[r * 3 + 0];
            qy[q] = Q[r * 3 + 1];
            qz[q] = Q[r * 3 + 2];
            qq[q] = fmaf(qx[q], qx[q], fmaf(qy[q], qy[q], qz[q] * qz[q]));
        }

        float m[4];
        #pragma unroll
        for (int q = 0; q < 4; q++) m[q] = 3.0e38f;

        volatile float* cm = cmin + (tid >> 5) * 64;
        const int cbase = tid & 63;

        #pragma unroll 4
        for (int k = 0; k < SLEN; k++) {
            const int c = cbase ^ k;      // lanes in a warp hit distinct cols
            const float4 sv = tile[c];
            float v0 = fmaf(sv.x, qx[0], fmaf(sv.y, qy[0], fmaf(sv.z, qz[0], qq[0]))) + sv.w;
            float v1 = fmaf(sv.x, qx[1], fmaf(sv.y, qy[1], fmaf(sv.z, qz[1], qq[1]))) + sv.w;
            float v2 = fmaf(sv.x, qx[2], fmaf(sv.y, qy[2], fmaf(sv.z, qz[2], qq[2]))) + sv.w;
            float v3 = fmaf(sv.x, qx[3], fmaf(sv.y, qy[3], fmaf(sv.z, qz[3], qq[3]))) + sv.w;
            m[0] = fminf(m[0], v0);
            m[1] = fminf(m[1], v1);
            m[2] = fminf(m[2], v2);
            m[3] = fminf(m[3], v3);
            float tv = fminf(fminf(v0, v1), fminf(v2, v3));
            cm[c] = fminf(cm[c], tv);
        }

        unsigned int* dst = g_min + b * 2048 + rh * 1024;
        #pragma unroll
        for (int q = 0; q < 4; q++)
            atomicMax(&dst[tid + 256 * q], enc_min(m[q]));

        __syncthreads();
        if (tid < SLEN) {
            float mc = cmin[tid];
            #pragma unroll
            for (int w = 1; w < 8; w++) mc = fminf(mc, cmin[w * 64 + tid]);
            atomicMax(&g_min[16384 + b * 2048 + sl * SLEN + tid], enc_min(mc));
        }

        // ---- group finalize ----
        __threadfence();
        if (tid == 0) {
            s_g1 = atomicAdd(&g_cnt_row[b * 2 + rh], 1u);
            s_g2 = atomicAdd(&g_cnt_col[b], 1u);
        }
        __syncthreads();

        if (s_g1 == 31u) {  // last slice for this row group: decode 1024 rows
            __threadfence();
            const int base = b * 2048 + rh * 1024 + tid * 4;
            uint4 u = __ldcg((const uint4*)(g_min + base));
            *(uint4*)(g_min + base) = make_uint4(0u, 0u, 0u, 0u);
            float su = dec_sqrt(u.x) + dec_sqrt(u.y) + dec_sqrt(u.z) + dec_sqrt(u.w);
            float tot = block_sum(su, s_red);
            if (tid == 0) {
                g_gsum[b * 2 + rh] = tot * (0.5f / (BATCH * NPTS));
                g_cnt_row[b * 2 + rh] = 0u;
            }
        }
        if (s_g2 == 63u) {  // last block for this batch: decode 2048 cols
            __threadfence();
            float su = 0.0f;
            #pragma unroll
            for (int i = 0; i < 2; i++) {
                const int base = 16384 + b * 2048 + i * 1024 + tid * 4;
                uint4 u = __ldcg((const uint4*)(g_min + base));
                *(uint4*)(g_min + base) = make_uint4(0u, 0u, 0u, 0u);
                su += dec_sqrt(u.x) + dec_sqrt(u.y) + dec_sqrt(u.z) + dec_sqrt(u.w);
            }
            float tot = block_sum(su, s_red);
            if (tid == 0) {
                g_gsum[16 + b] = tot * (0.5f / (BATCH * NPTS));
                g_cnt_col[b] = 0u;
            }
        }
    } else {
        const int id = bid - 512;
        if (id < 32) {
            // dir2: pts -> kpt, 512-row segment (2 rows/thread), 128 targets
            const int b = id >> 2;
            const int seg = id & 3;
            const float* Q = pts + (size_t)b * NPTS * 3;
            const float* T = kpt + (size_t)b * KPT * 3;
            float4* tile = (float4*)s_buf;
            if (tid < KPT) {
                float x = T[tid * 3 + 0];
                float y = T[tid * 3 + 1];
                float z = T[tid * 3 + 2];
                float w = fmaf(x, x, fmaf(y, y, z * z));
                tile[tid] = make_float4(-2.0f * x, -2.0f * y, -2.0f * z, w);
            }
            __syncthreads();

            const int rowbase = seg * 512;
            float sum = 0.0f;
            #pragma unroll
            for (int q = 0; q < 2; q++) {
                const int r = rowbase + tid + 256 * q;
                float qx = Q[r * 3 + 0];
                float qy = Q[r * 3 + 1];
                float qz = Q[r * 3 + 2];
                float q2 = fmaf(qx, qx, fmaf(qy, qy, qz * qz));
                float mm = 3.0e38f;
                #pragma unroll 8
                for (int t = 0; t < KPT; t++) {
                    float4 sv = tile[t];
                    float v = fmaf(sv.x, qx, fmaf(sv.y, qy, fmaf(sv.z, qz, sv.w)));
                    mm = fminf(mm, v);
                }
                sum += sqrt_fast(fmaxf(q2 + mm, 0.0f));
            }
            float tot = block_sum(sum, s_red);
            if (tid == 0) g_slots[id] = tot * (0.5f / (BATCH * NPTS));
        } else if (id < 64) {
            // dir3: kpt -> pts. 256 threads = (query q, target half h).
            const int j = id - 32;
            const int b = j >> 2;
            const int quarter = j & 3;
            const float* Q = kpt + (size_t)b * KPT * 3;
            const float* T = pts + (size_t)b * NPTS * 3 + quarter * 512 * 3;
            float4* tile = (float4*)s_buf;  // 512 x 16B = 8KB
            #pragma unroll
            for (int jj = tid; jj < 512; jj += THREADS) {
                float x = T[jj * 3 + 0];
                float y = T[jj * 3 + 1];
                float z = T[jj * 3 + 2];
                float w = fmaf(x, x, fmaf(y, y, z * z));
                tile[jj] = make_float4(-2.0f * x, -2.0f * y, -2.0f * z, w);
            }
            __syncthreads();

            const int q = tid & 127;
            const int h = tid >> 7;
            float qx = Q[q * 3 + 0];
            float qy = Q[q * 3 + 1];
            float qz = Q[q * 3 + 2];
            float q2 = fmaf(qx, qx, fmaf(qy, qy, qz * qz));
            const float4* tl = tile + h * 256;
            float mm = 3.0e38f;
            #pragma unroll 8
            for (int t = 0; t < 256; t++) {
                float4 sv = tl[t];
                float v = fmaf(sv.x, qx, fmaf(sv.y, qy, fmaf(sv.z, qz, sv.w)));
                mm = fminf(mm, v);
            }
            atomicMax(&g_d3min[b * KPT + q], enc_min(q2 + mm));

            // ---- dir3 group finalize ----
            __threadfence();
            if (tid == 0) s_g1 = atomicAdd(&g_cnt_d3, 1u);
            __syncthreads();
            if (s_g1 == 31u) {
                __threadfence();
                const int base = tid * 4;
                uint4 u = __ldcg((const uint4*)(g_d3min + base));
                *(uint4*)(g_d3min + base) = make_uint4(0u, 0u, 0u, 0u);
                float su = dec_sqrt(u.x) + dec_sqrt(u.y) + dec_sqrt(u.z) + dec_sqrt(u.w);
                float tot = block_sum(su, s_red);
                if (tid == 0) {
                    g_gsum[24] = tot * (0.5f / (BATCH * KPT));
                    g_cnt_d3 = 0u;
                }
            }
        } else {
            // smalls: pose + NOCS + diversity + delta per batch
            const int b = id - 64;
            float* sk = (float*)s_buf;
            const float* K = kpt + (size_t)b * KPT * 3;
            for (int i = tid; i < KPT * 3; i += THREADS) sk[i] = K[i];
            __syncthreads();

            float acc = 0.0f;
            const float invDiv = 1.0f / (float)(BATCH * KPT * KPT);
            for (int p = tid; p < KPT * KPT; p += THREADS) {
                const int i = p >> 7;
                const int jj = p & 127;
                float c;
                if (i == jj) {
                    c = 0.1f;
                } else {
                    float dx = sk[i * 3 + 0] - sk[jj * 3 + 0];
                    float dy = sk[i * 3 + 1] - sk[jj * 3 + 1];
                    float dz = sk[i * 3 + 2] - sk[jj * 3 + 2];
                    c = fminf(sqrt_fast(fmaf(dx, dx, fmaf(dy, dy, dz * dz))), 0.1f);
                }
                acc += c * invDiv;
            }

            if (tid < KPT) {
                const float* R = gt_R + (size_t)b * 9;
                const float t0 = gt_t[b * 3 + 0], t1 = gt_t[b * 3 + 1], t2 = gt_t[b * 3 + 2];
                const float s0 = gt_s[b * 3 + 0], s1 = gt_s[b * 3 + 1], s2 = gt_s[b * 3 + 2];
                const float scale = sqrtf(s0 * s0 + s1 * s1 + s2 * s2) + 1e-8f;
                const float inv = 1.0f / scale;
                const float px = (sk[tid * 3 + 0] - t0) * inv;
                const float py = (sk[tid * 3 + 1] - t1) * inv;
                const float pz = (sk[tid * 3 + 2] - t2) * inv;
                const float* pn = pred_nocs + ((size_t)b * KPT + tid) * 3;
                float sl = 0.0f;
                #pragma unroll
                for (int jj = 0; jj < 3; jj++) {
                    float g = px * R[jj] + py * R[3 + jj] + pz * R[6 + jj];
                    float d = fabsf(pn[jj] - g);
                    sl += (d > 0.1f) ? (d - 0.05f) : (d * d * 5.0f);
                }
                acc += sl * (1.0f / (float)(BATCH * KPT));
            }

            const float* D = recon_delta + (size_t)b * NPTS * 3;
            float dsum = 0.0f;
            for (int r = tid; r < NPTS; r += THREADS) {
                float x = D[r * 3 + 0];
                float y = D[r * 3 + 1];
                float z = D[r * 3 + 2];
                dsum += sqrt_fast(fmaf(x, x, fmaf(y, y, z * z)));
            }
            acc += dsum * (1.0f / (float)(BATCH * NPTS));

            float tot = block_sum(acc, s_red);
            if (tid == 0) {
                const float* Rp = pred_R + (size_t)b * 9;
                const float* Rg = gt_R + (size_t)b * 9;
                float cs = 0.0f;
                #pragma unroll
                for (int jj = 0; jj < 3; jj++) {
                    float a0 = Rp[jj]     - Rg[jj];
                    float a1 = Rp[3 + jj] - Rg[3 + jj];
                    float a2 = Rp[6 + jj] - Rg[6 + jj];
                    cs += sqrtf(a0 * a0 + a1 * a1 + a2 * a2);
                }
                float dt0 = pred_t[b * 3 + 0] - gt_t[b * 3 + 0];
                float dt1 = pred_t[b * 3 + 1] - gt_t[b * 3 + 1];
                float dt2 = pred_t[b * 3 + 2] - gt_t[b * 3 + 2];
                float tn = sqrtf(dt0 * dt0 + dt1 * dt1 + dt2 * dt2);
                float ds0 = pred_s[b * 3 + 0] - gt_s[b * 3 + 0];
                float ds1 = pred_s[b * 3 + 1] - gt_s[b * 3 + 1];
                float ds2 = pred_s[b * 3 + 2] - gt_s[b * 3 + 2];
                float sn = sqrtf(ds0 * ds0 + ds1 * ds1 + ds2 * ds2);
                g_slots[32 + b] = tot
                                + cs * (1.0f / (3.0f * BATCH))
                                + tn * (1.0f / BATCH)
                                + sn * (1.0f / BATCH);
            }
        }
    }

    // ===== global epilogue: last block sums 65 scalars =====
    __syncthreads();
    if (tid == 0) {
        __threadfence();
        s_rank = atomicAdd(&g_count, 1u);
    }
    __syncthreads();
    if (s_rank != NBLOCKS - 1u) return;

    __threadfence();
    float a = 0.0f;
    if (tid < 25) a += __ldcg(g_gsum + tid);
    if (tid >= 32 && tid < 72) a += __ldcg(g_slots + (tid - 32));

    float tot = block_sum(a, s_red);
    if (tid == 0) {
        out[0] = tot;
        g_count = 0;  // reset for graph replay
    }
}

extern "C" void kernel_launch(void* const* d_in, const int* in_sizes, int n_in,
                              void* d_out, int out_size) {
    const float* pts         = (const float*)d_in[0];
    const float* recon_delta = (const float*)d_in[1];
    const float* kpt         = (const float*)d_in[2];
    const float* recon       = (const float*)d_in[3];
    const float* pred_nocs   = (const float*)d_in[4];
    const float* pred_R      = (const float*)d_in[5];
    const float* pred_t      = (const float*)d_in[6];
    const float* pred_s      = (const float*)d_in[7];
    const float* gt_R        = (const float*)d_in[8];
    const float* gt_t        = (const float*)d_in[9];
    const float* gt_s        = (const float*)d_in[10];

    fused<<<NBLOCKS, THREADS>>>(pts, recon, kpt, recon_delta, pred_nocs,
                                pred_R, pred_t, pred_s, gt_R, gt_t, gt_s,
                                (float*)d_out);
}